// round 1
// baseline (speedup 1.0000x reference)
#include <cuda_runtime.h>
#include <cuda_bf16.h>
#include <math.h>
#include <stdint.h>

// Problem dims
#define Bz 32
#define Sz 128
#define Ez 512
#define Hz 1024
#define Gz 4096   // 4*H
#define Lz 128
#define Vz 32000
#define TDz 126   // S-2

// ---------------- scratch (device globals; no runtime allocation) ----------------
__device__ float g_Xe[Sz * Bz * Ez];              // encoder embedded inputs, time-major rows (t*B+b)
__device__ float g_Pe[(size_t)Sz * Bz * Gz];      // encoder x@Wih^T + biases
__device__ float g_hse[(Sz + 1) * Bz * Hz];       // encoder hidden history, slot 0 = h0 (zeros)
__device__ float g_Xd[TDz * Bz * Ez];
__device__ float g_Pd[(size_t)TDz * Bz * Gz];
__device__ float g_hsd[(TDz + 1) * Bz * Hz];      // decoder hidden history, slot 0 = h0 (latent)
__device__ float g_c[Bz * Hz];                    // LSTM cell state (reused enc->dec)

// ---------------- f32x2 helpers ----------------
__device__ __forceinline__ unsigned long long pk2(float x, float y) {
    unsigned long long r;
    asm("mov.b64 %0, {%1,%2};" : "=l"(r) : "f"(x), "f"(y));
    return r;
}
__device__ __forceinline__ float2 upk2(unsigned long long v) {
    float2 r;
    asm("mov.b64 {%0,%1}, %2;" : "=f"(r.x), "=f"(r.y) : "l"(v));
    return r;
}
__device__ __forceinline__ unsigned long long ffma2(unsigned long long a, unsigned long long b,
                                                    unsigned long long c) {
    unsigned long long d;
    asm("fma.rn.f32x2 %0, %1, %2, %3;" : "=l"(d) : "l"(a), "l"(b), "l"(c));
    return d;
}

__device__ __forceinline__ float sigm(float x) { return 1.0f / (1.0f + expf(-x)); }

// ---------------- tiny init: zero h0 (encoder) and c ----------------
__global__ void zero2_kernel(float* __restrict__ a, float* __restrict__ b, int n) {
    int i = blockIdx.x * blockDim.x + threadIdx.x;
    int stride = gridDim.x * blockDim.x;
    for (; i < n; i += stride) { a[i] = 0.0f; b[i] = 0.0f; }
}

// ---------------- embedding gather (time-major) ----------------
// X[(t*B + b)*E + e] = emb[tokens[b*S + t + toff]*E + e]
__global__ void embed_kernel(const int* __restrict__ tokens, const float* __restrict__ emb,
                             float* __restrict__ X, int T, int toff) {
    int total4 = T * Bz * (Ez / 4);
    int i = blockIdx.x * blockDim.x + threadIdx.x;
    int stride = gridDim.x * blockDim.x;
    const int E4 = Ez / 4;
    for (; i < total4; i += stride) {
        int e4 = i % E4;
        int r  = i / E4;        // t*B + b
        int b  = r % Bz;
        int t  = r / Bz;
        int tok = tokens[b * Sz + t + toff];
        ((float4*)X)[i] = ((const float4*)(emb + (size_t)tok * Ez))[e4];
    }
}

// ---------------- generic NT SGEMM: C[m][n] = sum_k A[m][k]*W[n][k] (+bias) ----------------
// BM=BN=128, BK=16, 256 threads, 8x8 thread tile, f32x2 FMAs.
// mode 0: C[m*N+n] = acc + bias1[n] + bias2[n]
// mode 1: (logits) m = t*B+b -> C[(b*TD + t)*N + n] = acc + bias1[n]
__global__ __launch_bounds__(256, 2)
void sgemm_nt_kernel(const float* __restrict__ A, const float* __restrict__ W,
                     float* __restrict__ C, int M, int N, int K,
                     const float* __restrict__ bias1, const float* __restrict__ bias2, int mode) {
    __shared__ float As[16][132];
    __shared__ float Bs[16][132];

    const int n0 = blockIdx.x * 128;
    const int m0 = blockIdx.y * 128;
    const int tid = threadIdx.x;
    const int tx = tid & 15;   // n tile index
    const int ty = tid >> 4;   // m tile index
    const int lm = tid >> 2;   // 0..63  load row
    const int lk4 = tid & 3;   // 0..3   float4 column within BK

    unsigned long long c2[8][4];
#pragma unroll
    for (int i = 0; i < 8; i++)
#pragma unroll
        for (int j = 0; j < 4; j++) c2[i][j] = 0ull;

    for (int k0 = 0; k0 < K; k0 += 16) {
        // load A tile (with M guard), transposed into As[k][m]
#pragma unroll
        for (int r = 0; r < 2; r++) {
            int m = lm + r * 64;
            float4 v = make_float4(0.f, 0.f, 0.f, 0.f);
            int gm = m0 + m;
            if (gm < M) v = *(const float4*)(A + (size_t)gm * K + k0 + lk4 * 4);
            As[lk4 * 4 + 0][m] = v.x;
            As[lk4 * 4 + 1][m] = v.y;
            As[lk4 * 4 + 2][m] = v.z;
            As[lk4 * 4 + 3][m] = v.w;
        }
        // load W tile (N always multiple of 128), transposed into Bs[k][n]
#pragma unroll
        for (int r = 0; r < 2; r++) {
            int n = lm + r * 64;
            float4 v = *(const float4*)(W + (size_t)(n0 + n) * K + k0 + lk4 * 4);
            Bs[lk4 * 4 + 0][n] = v.x;
            Bs[lk4 * 4 + 1][n] = v.y;
            Bs[lk4 * 4 + 2][n] = v.z;
            Bs[lk4 * 4 + 3][n] = v.w;
        }
        __syncthreads();

#pragma unroll
        for (int kk = 0; kk < 16; kk++) {
            float a[8];
            *(float4*)(&a[0]) = *(const float4*)(&As[kk][ty * 8]);
            *(float4*)(&a[4]) = *(const float4*)(&As[kk][ty * 8 + 4]);
            float b[8];
            *(float4*)(&b[0]) = *(const float4*)(&Bs[kk][tx * 8]);
            *(float4*)(&b[4]) = *(const float4*)(&Bs[kk][tx * 8 + 4]);
            unsigned long long b2[4];
#pragma unroll
            for (int j = 0; j < 4; j++) b2[j] = pk2(b[2 * j], b[2 * j + 1]);
#pragma unroll
            for (int i = 0; i < 8; i++) {
                unsigned long long a2 = pk2(a[i], a[i]);
#pragma unroll
                for (int j = 0; j < 4; j++) c2[i][j] = ffma2(a2, b2[j], c2[i][j]);
            }
        }
        __syncthreads();
    }

    // epilogue
#pragma unroll
    for (int i = 0; i < 8; i++) {
        int m = m0 + ty * 8 + i;
        if (m >= M) continue;
        size_t rowbase;
        if (mode == 0) {
            rowbase = (size_t)m * N;
        } else {
            int bb = m & (Bz - 1);
            int tt = m >> 5;
            rowbase = (size_t)(bb * TDz + tt) * N;
        }
#pragma unroll
        for (int j = 0; j < 4; j++) {
            float2 v = upk2(c2[i][j]);
            int n = n0 + tx * 8 + 2 * j;
            float add0 = bias1[n], add1 = bias1[n + 1];
            if (mode == 0) { add0 += bias2[n]; add1 += bias2[n + 1]; }
            C[rowbase + n]     = v.x + add0;
            C[rowbase + n + 1] = v.y + add1;
        }
    }
}

// ---------------- fused LSTM step ----------------
// grid (16, 32): blockIdx.x -> 64-unit tile u0, blockIdx.y -> batch b.
// 8 warps: warp w handles gate gp=w>>1, half hi=w&1 (32 rows each).
// Lane owns k in [lane*32, lane*32+32); h row cached in registers.
__global__ __launch_bounds__(256)
void lstm_step_kernel(const float* __restrict__ Whh, const float* __restrict__ P,
                      const float* __restrict__ hin, float* __restrict__ hout,
                      float* __restrict__ c) {
    const int b = blockIdx.y;
    const int u0 = blockIdx.x * 64;
    const int tid = threadIdx.x;
    const int w = tid >> 5;
    const int lane = tid & 31;
    const int gp = w >> 1;
    const int hi = w & 1;

    __shared__ float sg[4][64];

    // preload this batch's h (32 floats per lane, as 8x 16B)
    const ulonglong2* hrow = (const ulonglong2*)(hin + b * Hz);
    unsigned long long hp[16];
#pragma unroll
    for (int i = 0; i < 8; i++) {
        ulonglong2 v = hrow[lane * 8 + i];
        hp[2 * i]     = v.x;
        hp[2 * i + 1] = v.y;
    }

#pragma unroll 2
    for (int jj = 0; jj < 32; jj++) {
        int row = gp * 1024 + u0 + hi * 32 + jj;
        const ulonglong2* wr = (const ulonglong2*)(Whh + (size_t)row * Hz);
        unsigned long long acc = 0ull;
#pragma unroll
        for (int i = 0; i < 8; i++) {
            ulonglong2 wv = wr[lane * 8 + i];
            acc = ffma2(wv.x, hp[2 * i], acc);
            acc = ffma2(wv.y, hp[2 * i + 1], acc);
        }
        float2 p2 = upk2(acc);
        float s = p2.x + p2.y;
#pragma unroll
        for (int off = 16; off > 0; off >>= 1)
            s += __shfl_xor_sync(0xffffffffu, s, off);
        if (lane == 0)
            sg[gp][hi * 32 + jj] = s + P[(size_t)b * Gz + row];
    }
    __syncthreads();

    if (tid < 64) {
        int u = u0 + tid;
        float gi = sg[0][tid];
        float gf = sg[1][tid];
        float gg = sg[2][tid];
        float go = sg[3][tid];
        float cc = c[b * Hz + u];
        cc = sigm(gf) * cc + sigm(gi) * tanhf(gg);
        float hh = sigm(go) * tanhf(cc);
        c[b * Hz + u] = cc;
        hout[b * Hz + u] = hh;
    }
}

// ---------------- latent head: last_h -> mean, log_var, z, h0_dec; reset c ----------------
__global__ __launch_bounds__(256)
void latent_kernel(const int* __restrict__ tokens, const float* __restrict__ hs,
                   const float* __restrict__ Wmu, const float* __restrict__ bmu,
                   const float* __restrict__ Wlv, const float* __restrict__ blv,
                   const float* __restrict__ eps,
                   const float* __restrict__ Wl2h, const float* __restrict__ bl2h,
                   float* __restrict__ out_mean, float* __restrict__ out_lv,
                   float* __restrict__ hd0, float* __restrict__ c) {
    const int b = blockIdx.x;
    const int tid = threadIdx.x;

    __shared__ int scnt[256];
    __shared__ float smean[128];
    __shared__ float slv[128];
    __shared__ float sz[128];

    int cnt = 0;
    if (tid < Sz) cnt = (tokens[b * Sz + tid] != 0) ? 1 : 0;
    scnt[tid] = cnt;
    __syncthreads();
    for (int off = 128; off >= 1; off >>= 1) {
        if (tid < off) scnt[tid] += scnt[tid + off];
        __syncthreads();
    }
    int last = scnt[0] - 1;
    if (last < 0) last = 0;

    const float* lh = hs + (size_t)(last + 1) * Bz * Hz + (size_t)b * Hz;

    {
        int j = tid & 127;
        const float* Wr = ((tid < 128) ? Wmu : Wlv) + (size_t)j * Hz;
        float acc = 0.f;
        const float4* l4 = (const float4*)lh;
        const float4* w4 = (const float4*)Wr;
#pragma unroll 4
        for (int k = 0; k < Hz / 4; k++) {
            float4 a = l4[k];
            float4 ww = w4[k];
            acc += a.x * ww.x + a.y * ww.y + a.z * ww.z + a.w * ww.w;
        }
        if (tid < 128) smean[j] = acc + bmu[j];
        else           slv[j]   = acc + blv[j];
    }
    __syncthreads();

    if (tid < 128) {
        float m = smean[tid];
        float lv = slv[tid];
        out_mean[b * Lz + tid] = m;
        out_lv[b * Lz + tid] = lv;
        sz[tid] = m + eps[b * Lz + tid] * expf(0.5f * lv);
    }
    __syncthreads();

#pragma unroll
    for (int r = 0; r < 4; r++) {
        int u = tid + r * 256;
        float acc = bl2h[u];
        const float* wr = Wl2h + (size_t)u * Lz;
#pragma unroll 4
        for (int l = 0; l < Lz; l++) acc += sz[l] * wr[l];
        hd0[b * Hz + u] = acc;
        c[b * Hz + u] = 0.f;
    }
}

// ---------------- launch ----------------
extern "C" void kernel_launch(void* const* d_in, const int* in_sizes, int n_in,
                              void* d_out, int out_size) {
    const int*   tokens  = (const int*)d_in[0];
    const float* emb_enc = (const float*)d_in[1];
    const float* Wih_e   = (const float*)d_in[2];
    const float* Whh_e   = (const float*)d_in[3];
    const float* bih_e   = (const float*)d_in[4];
    const float* bhh_e   = (const float*)d_in[5];
    const float* W_mu    = (const float*)d_in[6];
    const float* b_mu    = (const float*)d_in[7];
    const float* W_lv    = (const float*)d_in[8];
    const float* b_lv    = (const float*)d_in[9];
    const float* emb_dec = (const float*)d_in[10];
    const float* W_l2h   = (const float*)d_in[11];
    const float* b_l2h   = (const float*)d_in[12];
    const float* Wih_d   = (const float*)d_in[13];
    const float* Whh_d   = (const float*)d_in[14];
    const float* bih_d   = (const float*)d_in[15];
    const float* bhh_d   = (const float*)d_in[16];
    const float* W_out   = (const float*)d_in[17];
    const float* b_out   = (const float*)d_in[18];
    const float* epsv    = (const float*)d_in[19];

    float* out = (float*)d_out;
    const size_t LOGITS = (size_t)Bz * TDz * Vz;
    float* out_logits = out;
    float* out_mean   = out + LOGITS;
    float* out_lv     = out + LOGITS + (size_t)Bz * Lz;

    float *p_Xe, *p_Pe, *p_hse, *p_Xd, *p_Pd, *p_hsd, *p_c;
    cudaGetSymbolAddress((void**)&p_Xe,  g_Xe);
    cudaGetSymbolAddress((void**)&p_Pe,  g_Pe);
    cudaGetSymbolAddress((void**)&p_hse, g_hse);
    cudaGetSymbolAddress((void**)&p_Xd,  g_Xd);
    cudaGetSymbolAddress((void**)&p_Pd,  g_Pd);
    cudaGetSymbolAddress((void**)&p_hsd, g_hsd);
    cudaGetSymbolAddress((void**)&p_c,   g_c);

    // 1) zero encoder h0 slot and c
    zero2_kernel<<<64, 256>>>(p_hse, p_c, Bz * Hz);

    // 2) embeddings
    embed_kernel<<<2048, 256>>>(tokens, emb_enc, p_Xe, Sz, 0);
    embed_kernel<<<2048, 256>>>(tokens, emb_dec, p_Xd, TDz, 1);

    // 3) input projections (hoisted out of the recurrences)
    {
        dim3 grid(Gz / 128, (Sz * Bz + 127) / 128);
        sgemm_nt_kernel<<<grid, 256>>>(p_Xe, Wih_e, p_Pe, Sz * Bz, Gz, Ez, bih_e, bhh_e, 0);
    }
    {
        dim3 grid(Gz / 128, (TDz * Bz + 127) / 128);
        sgemm_nt_kernel<<<grid, 256>>>(p_Xd, Wih_d, p_Pd, TDz * Bz, Gz, Ez, bih_d, bhh_d, 0);
    }

    // 4) encoder recurrence
    {
        dim3 grid(16, Bz);
        for (int t = 0; t < Sz; t++) {
            lstm_step_kernel<<<grid, 256>>>(Whh_e,
                                            p_Pe + (size_t)t * Bz * Gz,
                                            p_hse + (size_t)t * Bz * Hz,
                                            p_hse + (size_t)(t + 1) * Bz * Hz,
                                            p_c);
        }
    }

    // 5) latent head (also writes decoder h0 into g_hsd slot 0, zeroes c)
    latent_kernel<<<Bz, 256>>>(tokens, p_hse, W_mu, b_mu, W_lv, b_lv, epsv,
                               W_l2h, b_l2h, out_mean, out_lv, p_hsd, p_c);

    // 6) decoder recurrence
    {
        dim3 grid(16, Bz);
        for (int t = 0; t < TDz; t++) {
            lstm_step_kernel<<<grid, 256>>>(Whh_d,
                                            p_Pd + (size_t)t * Bz * Gz,
                                            p_hsd + (size_t)t * Bz * Hz,
                                            p_hsd + (size_t)(t + 1) * Bz * Hz,
                                            p_c);
        }
    }

    // 7) output projection -> logits (with (t,b)->(b,t) remap in epilogue)
    {
        dim3 grid(Vz / 128, (TDz * Bz + 127) / 128);
        sgemm_nt_kernel<<<grid, 256>>>(p_hsd + (size_t)Bz * Hz, W_out, out_logits,
                                       TDz * Bz, Vz, Hz, b_out, b_out, 1);
    }
}

// round 2
// speedup vs baseline: 3.3294x; 3.3294x over previous
#include <cuda_runtime.h>
#include <cuda_bf16.h>
#include <math.h>
#include <stdint.h>

// Problem dims
#define Bz 32
#define Sz 128
#define Ez 512
#define Hz 1024
#define Gz 4096   // 4*H
#define Lz 128
#define Vz 32000
#define TDz 126   // S-2

// ---------------- scratch (device globals; no runtime allocation) ----------------
__device__ float g_Xe[Sz * Bz * Ez];              // encoder embedded inputs, time-major rows (t*B+b)
__device__ float g_Pe[(size_t)Sz * Bz * Gz];      // encoder x@Wih^T + biases
__device__ float g_hse[(Sz + 1) * Bz * Hz];       // encoder hidden history, slot 0 = h0 (zeros)
__device__ float g_Xd[TDz * Bz * Ez];
__device__ float g_Pd[(size_t)TDz * Bz * Gz];
__device__ float g_hsd[(TDz + 1) * Bz * Hz];      // decoder hidden history, slot 0 = h0 (latent)
__device__ float g_c[Bz * Hz];                    // LSTM cell state (reused enc->dec)

// ---------------- f32x2 helpers ----------------
__device__ __forceinline__ unsigned long long pk2(float x, float y) {
    unsigned long long r;
    asm("mov.b64 %0, {%1,%2};" : "=l"(r) : "f"(x), "f"(y));
    return r;
}
__device__ __forceinline__ float2 upk2(unsigned long long v) {
    float2 r;
    asm("mov.b64 {%0,%1}, %2;" : "=f"(r.x), "=f"(r.y) : "l"(v));
    return r;
}
__device__ __forceinline__ unsigned long long ffma2(unsigned long long a, unsigned long long b,
                                                    unsigned long long c) {
    unsigned long long d;
    asm("fma.rn.f32x2 %0, %1, %2, %3;" : "=l"(d) : "l"(a), "l"(b), "l"(c));
    return d;
}

__device__ __forceinline__ float sigm(float x) { return 1.0f / (1.0f + expf(-x)); }

// ---------------- tiny init: zero h0 (encoder) and c ----------------
__global__ void zero2_kernel(float* __restrict__ a, float* __restrict__ b, int n) {
    int i = blockIdx.x * blockDim.x + threadIdx.x;
    int stride = gridDim.x * blockDim.x;
    for (; i < n; i += stride) { a[i] = 0.0f; b[i] = 0.0f; }
}

// ---------------- embedding gather (time-major) ----------------
// X[(t*B + b)*E + e] = emb[tokens[b*S + t + toff]*E + e]
__global__ void embed_kernel(const int* __restrict__ tokens, const float* __restrict__ emb,
                             float* __restrict__ X, int T, int toff) {
    int total4 = T * Bz * (Ez / 4);
    int i = blockIdx.x * blockDim.x + threadIdx.x;
    int stride = gridDim.x * blockDim.x;
    const int E4 = Ez / 4;
    for (; i < total4; i += stride) {
        int e4 = i % E4;
        int r  = i / E4;        // t*B + b
        int b  = r % Bz;
        int t  = r / Bz;
        int tok = tokens[b * Sz + t + toff];
        ((float4*)X)[i] = ((const float4*)(emb + (size_t)tok * Ez))[e4];
    }
}

// ---------------- generic NT SGEMM: C[m][n] = sum_k A[m][k]*W[n][k] (+bias) ----------------
// BM=BN=128, BK=16, 256 threads, 8x8 thread tile, f32x2 FMAs.
// mode 0: C[m*N+n] = acc + bias1[n] + bias2[n]
// mode 1: (logits) m = t*B+b -> C[(b*TD + t)*N + n] = acc + bias1[n]
__global__ __launch_bounds__(256, 2)
void sgemm_nt_kernel(const float* __restrict__ A, const float* __restrict__ W,
                     float* __restrict__ C, int M, int N, int K,
                     const float* __restrict__ bias1, const float* __restrict__ bias2, int mode) {
    __shared__ float As[16][132];
    __shared__ float Bs[16][132];

    const int n0 = blockIdx.x * 128;
    const int m0 = blockIdx.y * 128;
    const int tid = threadIdx.x;
    const int tx = tid & 15;   // n tile index
    const int ty = tid >> 4;   // m tile index
    const int lm = tid >> 2;   // 0..63  load row
    const int lk4 = tid & 3;   // 0..3   float4 column within BK

    unsigned long long c2[8][4];
#pragma unroll
    for (int i = 0; i < 8; i++)
#pragma unroll
        for (int j = 0; j < 4; j++) c2[i][j] = 0ull;

    for (int k0 = 0; k0 < K; k0 += 16) {
        // load A tile (with M guard), transposed into As[k][m]
#pragma unroll
        for (int r = 0; r < 2; r++) {
            int m = lm + r * 64;
            float4 v = make_float4(0.f, 0.f, 0.f, 0.f);
            int gm = m0 + m;
            if (gm < M) v = *(const float4*)(A + (size_t)gm * K + k0 + lk4 * 4);
            As[lk4 * 4 + 0][m] = v.x;
            As[lk4 * 4 + 1][m] = v.y;
            As[lk4 * 4 + 2][m] = v.z;
            As[lk4 * 4 + 3][m] = v.w;
        }
        // load W tile (N always multiple of 128), transposed into Bs[k][n]
#pragma unroll
        for (int r = 0; r < 2; r++) {
            int n = lm + r * 64;
            float4 v = *(const float4*)(W + (size_t)(n0 + n) * K + k0 + lk4 * 4);
            Bs[lk4 * 4 + 0][n] = v.x;
            Bs[lk4 * 4 + 1][n] = v.y;
            Bs[lk4 * 4 + 2][n] = v.z;
            Bs[lk4 * 4 + 3][n] = v.w;
        }
        __syncthreads();

#pragma unroll
        for (int kk = 0; kk < 16; kk++) {
            float a[8];
            *(float4*)(&a[0]) = *(const float4*)(&As[kk][ty * 8]);
            *(float4*)(&a[4]) = *(const float4*)(&As[kk][ty * 8 + 4]);
            float b[8];
            *(float4*)(&b[0]) = *(const float4*)(&Bs[kk][tx * 8]);
            *(float4*)(&b[4]) = *(const float4*)(&Bs[kk][tx * 8 + 4]);
            unsigned long long b2[4];
#pragma unroll
            for (int j = 0; j < 4; j++) b2[j] = pk2(b[2 * j], b[2 * j + 1]);
#pragma unroll
            for (int i = 0; i < 8; i++) {
                unsigned long long a2 = pk2(a[i], a[i]);
#pragma unroll
                for (int j = 0; j < 4; j++) c2[i][j] = ffma2(a2, b2[j], c2[i][j]);
            }
        }
        __syncthreads();
    }

    // epilogue
#pragma unroll
    for (int i = 0; i < 8; i++) {
        int m = m0 + ty * 8 + i;
        if (m >= M) continue;
        size_t rowbase;
        if (mode == 0) {
            rowbase = (size_t)m * N;
        } else {
            int bb = m & (Bz - 1);
            int tt = m >> 5;
            rowbase = (size_t)(bb * TDz + tt) * N;
        }
#pragma unroll
        for (int j = 0; j < 4; j++) {
            float2 v = upk2(c2[i][j]);
            int n = n0 + tx * 8 + 2 * j;
            float add0 = bias1[n], add1 = bias1[n + 1];
            if (mode == 0) { add0 += bias2[n]; add1 += bias2[n + 1]; }
            C[rowbase + n]     = v.x + add0;
            C[rowbase + n + 1] = v.y + add1;
        }
    }
}

// ---------------- fused LSTM step, batch-amortized ----------------
// grid(128), 256 threads. Block owns 8 hidden units (all 4 gates).
// Warp w owns unit u = blockIdx.x*8 + w; its 4 gate rows of Whh are
// REGISTER-RESIDENT (packed f32x2), read once per step. Loop over the 32
// batches streams h via LDG.128 (h is 128KB -> L1-resident), prefetching
// batch b+1 during the reduction of batch b. Gate sums land in smem; one
// parallel epilogue does the c/h update for all (unit, batch) pairs.
__global__ __launch_bounds__(256, 1)
void lstm_step_kernel(const float* __restrict__ Whh, const float* __restrict__ P,
                      const float* __restrict__ hin, float* __restrict__ hout,
                      float* __restrict__ c) {
    const int tid = threadIdx.x;
    const int w = tid >> 5;
    const int lane = tid & 31;
    const int u = blockIdx.x * 8 + w;    // global hidden unit for this warp

    __shared__ float sg[8][32][4];       // [unit_local][batch][gate]

    // Load the 4 gate rows of Whh for unit u: lane owns k = j*128 + 4*lane + {0..3}
    unsigned long long w2[4][8][2];
#pragma unroll
    for (int r = 0; r < 4; r++) {
        const float4* wr = (const float4*)(Whh + (size_t)(r * Hz + u) * Hz);
#pragma unroll
        for (int j = 0; j < 8; j++) {
            float4 v = wr[j * 32 + lane];
            w2[r][j][0] = pk2(v.x, v.y);
            w2[r][j][1] = pk2(v.z, v.w);
        }
    }

    const float4* h4 = (const float4*)hin;   // [batch][256 float4]
    float4 hv[8];
#pragma unroll
    for (int j = 0; j < 8; j++) hv[j] = h4[j * 32 + lane];   // batch 0

    for (int b = 0; b < Bz; b++) {
        unsigned long long acc[4];
#pragma unroll
        for (int r = 0; r < 4; r++) acc[r] = 0ull;

#pragma unroll
        for (int j = 0; j < 8; j++) {
            unsigned long long h01 = pk2(hv[j].x, hv[j].y);
            unsigned long long h23 = pk2(hv[j].z, hv[j].w);
#pragma unroll
            for (int r = 0; r < 4; r++) {
                acc[r] = ffma2(w2[r][j][0], h01, acc[r]);
                acc[r] = ffma2(w2[r][j][1], h23, acc[r]);
            }
        }

        // prefetch next batch's h while we reduce
        if (b + 1 < Bz) {
#pragma unroll
            for (int j = 0; j < 8; j++) hv[j] = h4[(b + 1) * 256 + j * 32 + lane];
        }

        // packed 4-value cross-lane reduction
        float2 p0 = upk2(acc[0]); float v0 = p0.x + p0.y;
        float2 p1 = upk2(acc[1]); float v1 = p1.x + p1.y;
        float2 p2 = upk2(acc[2]); float v2 = p2.x + p2.y;
        float2 p3 = upk2(acc[3]); float v3 = p3.x + p3.y;
        v0 += __shfl_xor_sync(0xffffffffu, v0, 1);
        v1 += __shfl_xor_sync(0xffffffffu, v1, 1);
        v2 += __shfl_xor_sync(0xffffffffu, v2, 1);
        v3 += __shfl_xor_sync(0xffffffffu, v3, 1);
        float a  = (lane & 1) ? v1 : v0;
        float bb = (lane & 1) ? v3 : v2;
        a  += __shfl_xor_sync(0xffffffffu, a, 2);
        bb += __shfl_xor_sync(0xffffffffu, bb, 2);
        float m = (lane & 2) ? bb : a;
        m += __shfl_xor_sync(0xffffffffu, m, 4);
        m += __shfl_xor_sync(0xffffffffu, m, 8);
        m += __shfl_xor_sync(0xffffffffu, m, 16);
        // lane holds the sum for gate r = lane & 3
        if (lane < 4) {
            float val = m + P[(size_t)b * Gz + lane * Hz + u];
            sg[w][b][lane] = val;
        }
    }
    __syncthreads();

    // epilogue: thread -> (unit_local = tid>>5, batch = tid&31)
    {
        int ul = tid >> 5;
        int b  = tid & 31;
        float gi = sg[ul][b][0];
        float gf = sg[ul][b][1];
        float gg = sg[ul][b][2];
        float go = sg[ul][b][3];
        int uu = blockIdx.x * 8 + ul;
        float cc = c[b * Hz + uu];
        cc = sigm(gf) * cc + sigm(gi) * tanhf(gg);
        float hh = sigm(go) * tanhf(cc);
        c[b * Hz + uu] = cc;
        hout[b * Hz + uu] = hh;
    }
}

// ---------------- latent head: last_h -> mean, log_var, z, h0_dec; reset c ----------------
__global__ __launch_bounds__(256)
void latent_kernel(const int* __restrict__ tokens, const float* __restrict__ hs,
                   const float* __restrict__ Wmu, const float* __restrict__ bmu,
                   const float* __restrict__ Wlv, const float* __restrict__ blv,
                   const float* __restrict__ eps,
                   const float* __restrict__ Wl2h, const float* __restrict__ bl2h,
                   float* __restrict__ out_mean, float* __restrict__ out_lv,
                   float* __restrict__ hd0, float* __restrict__ c) {
    const int b = blockIdx.x;
    const int tid = threadIdx.x;

    __shared__ int scnt[256];
    __shared__ float smean[128];
    __shared__ float slv[128];
    __shared__ float sz[128];

    int cnt = 0;
    if (tid < Sz) cnt = (tokens[b * Sz + tid] != 0) ? 1 : 0;
    scnt[tid] = cnt;
    __syncthreads();
    for (int off = 128; off >= 1; off >>= 1) {
        if (tid < off) scnt[tid] += scnt[tid + off];
        __syncthreads();
    }
    int last = scnt[0] - 1;
    if (last < 0) last = 0;

    const float* lh = hs + (size_t)(last + 1) * Bz * Hz + (size_t)b * Hz;

    {
        int j = tid & 127;
        const float* Wr = ((tid < 128) ? Wmu : Wlv) + (size_t)j * Hz;
        float acc = 0.f;
        const float4* l4 = (const float4*)lh;
        const float4* w4 = (const float4*)Wr;
#pragma unroll 4
        for (int k = 0; k < Hz / 4; k++) {
            float4 a = l4[k];
            float4 ww = w4[k];
            acc += a.x * ww.x + a.y * ww.y + a.z * ww.z + a.w * ww.w;
        }
        if (tid < 128) smean[j] = acc + bmu[j];
        else           slv[j]   = acc + blv[j];
    }
    __syncthreads();

    if (tid < 128) {
        float m = smean[tid];
        float lv = slv[tid];
        out_mean[b * Lz + tid] = m;
        out_lv[b * Lz + tid] = lv;
        sz[tid] = m + eps[b * Lz + tid] * expf(0.5f * lv);
    }
    __syncthreads();

#pragma unroll
    for (int r = 0; r < 4; r++) {
        int u = tid + r * 256;
        float acc = bl2h[u];
        const float* wr = Wl2h + (size_t)u * Lz;
#pragma unroll 4
        for (int l = 0; l < Lz; l++) acc += sz[l] * wr[l];
        hd0[b * Hz + u] = acc;
        c[b * Hz + u] = 0.f;
    }
}

// ---------------- launch ----------------
extern "C" void kernel_launch(void* const* d_in, const int* in_sizes, int n_in,
                              void* d_out, int out_size) {
    const int*   tokens  = (const int*)d_in[0];
    const float* emb_enc = (const float*)d_in[1];
    const float* Wih_e   = (const float*)d_in[2];
    const float* Whh_e   = (const float*)d_in[3];
    const float* bih_e   = (const float*)d_in[4];
    const float* bhh_e   = (const float*)d_in[5];
    const float* W_mu    = (const float*)d_in[6];
    const float* b_mu    = (const float*)d_in[7];
    const float* W_lv    = (const float*)d_in[8];
    const float* b_lv    = (const float*)d_in[9];
    const float* emb_dec = (const float*)d_in[10];
    const float* W_l2h   = (const float*)d_in[11];
    const float* b_l2h   = (const float*)d_in[12];
    const float* Wih_d   = (const float*)d_in[13];
    const float* Whh_d   = (const float*)d_in[14];
    const float* bih_d   = (const float*)d_in[15];
    const float* bhh_d   = (const float*)d_in[16];
    const float* W_out   = (const float*)d_in[17];
    const float* b_out   = (const float*)d_in[18];
    const float* epsv    = (const float*)d_in[19];

    float* out = (float*)d_out;
    const size_t LOGITS = (size_t)Bz * TDz * Vz;
    float* out_logits = out;
    float* out_mean   = out + LOGITS;
    float* out_lv     = out + LOGITS + (size_t)Bz * Lz;

    float *p_Xe, *p_Pe, *p_hse, *p_Xd, *p_Pd, *p_hsd, *p_c;
    cudaGetSymbolAddress((void**)&p_Xe,  g_Xe);
    cudaGetSymbolAddress((void**)&p_Pe,  g_Pe);
    cudaGetSymbolAddress((void**)&p_hse, g_hse);
    cudaGetSymbolAddress((void**)&p_Xd,  g_Xd);
    cudaGetSymbolAddress((void**)&p_Pd,  g_Pd);
    cudaGetSymbolAddress((void**)&p_hsd, g_hsd);
    cudaGetSymbolAddress((void**)&p_c,   g_c);

    // 1) zero encoder h0 slot and c
    zero2_kernel<<<64, 256>>>(p_hse, p_c, Bz * Hz);

    // 2) embeddings
    embed_kernel<<<2048, 256>>>(tokens, emb_enc, p_Xe, Sz, 0);
    embed_kernel<<<2048, 256>>>(tokens, emb_dec, p_Xd, TDz, 1);

    // 3) input projections (hoisted out of the recurrences)
    {
        dim3 grid(Gz / 128, (Sz * Bz + 127) / 128);
        sgemm_nt_kernel<<<grid, 256>>>(p_Xe, Wih_e, p_Pe, Sz * Bz, Gz, Ez, bih_e, bhh_e, 0);
    }
    {
        dim3 grid(Gz / 128, (TDz * Bz + 127) / 128);
        sgemm_nt_kernel<<<grid, 256>>>(p_Xd, Wih_d, p_Pd, TDz * Bz, Gz, Ez, bih_d, bhh_d, 0);
    }

    // 4) encoder recurrence
    for (int t = 0; t < Sz; t++) {
        lstm_step_kernel<<<128, 256>>>(Whh_e,
                                       p_Pe + (size_t)t * Bz * Gz,
                                       p_hse + (size_t)t * Bz * Hz,
                                       p_hse + (size_t)(t + 1) * Bz * Hz,
                                       p_c);
    }

    // 5) latent head (also writes decoder h0 into g_hsd slot 0, zeroes c)
    latent_kernel<<<Bz, 256>>>(tokens, p_hse, W_mu, b_mu, W_lv, b_lv, epsv,
                               W_l2h, b_l2h, out_mean, out_lv, p_hsd, p_c);

    // 6) decoder recurrence
    for (int t = 0; t < TDz; t++) {
        lstm_step_kernel<<<128, 256>>>(Whh_d,
                                       p_Pd + (size_t)t * Bz * Gz,
                                       p_hsd + (size_t)t * Bz * Hz,
                                       p_hsd + (size_t)(t + 1) * Bz * Hz,
                                       p_c);
    }

    // 7) output projection -> logits (with (t,b)->(b,t) remap in epilogue)
    {
        dim3 grid(Vz / 128, (TDz * Bz + 127) / 128);
        sgemm_nt_kernel<<<grid, 256>>>(p_hsd + (size_t)Bz * Hz, W_out, out_logits,
                                       TDz * Bz, Vz, Hz, b_out, b_out, 1);
    }
}

// round 3
// speedup vs baseline: 4.0861x; 1.2273x over previous
#include <cuda_runtime.h>
#include <cuda_bf16.h>
#include <math.h>
#include <stdint.h>

// Problem dims
#define Bz 32
#define Sz 128
#define Ez 512
#define Hz 1024
#define Gz 4096   // 4*H
#define Lz 128
#define Vz 32000
#define TDz 126   // S-2
#define NBLK 128  // persistent grid size

// ---------------- scratch (device globals; no runtime allocation) ----------------
__device__ float g_Xe[Sz * Bz * Ez];
__device__ float g_Pe[(size_t)Sz * Bz * Gz];
__device__ float g_hse[(Sz + 1) * Bz * Hz];
__device__ float g_Xd[TDz * Bz * Ez];
__device__ float g_Pd[(size_t)TDz * Bz * Gz];
__device__ float g_hsd[(TDz + 1) * Bz * Hz];
__device__ unsigned g_bar;                 // grid-barrier counter (reset each launch)

// ---------------- f32x2 helpers ----------------
__device__ __forceinline__ unsigned long long pk2(float x, float y) {
    unsigned long long r;
    asm("mov.b64 %0, {%1,%2};" : "=l"(r) : "f"(x), "f"(y));
    return r;
}
__device__ __forceinline__ float2 upk2(unsigned long long v) {
    float2 r;
    asm("mov.b64 {%0,%1}, %2;" : "=f"(r.x), "=f"(r.y) : "l"(v));
    return r;
}
__device__ __forceinline__ unsigned long long ffma2(unsigned long long a, unsigned long long b,
                                                    unsigned long long c) {
    unsigned long long d;
    asm("fma.rn.f32x2 %0, %1, %2, %3;" : "=l"(d) : "l"(a), "l"(b), "l"(c));
    return d;
}
__device__ __forceinline__ float sigm(float x) { return 1.0f / (1.0f + expf(-x)); }

// ---------------- grid barrier (all 128 blocks co-resident) ----------------
__device__ __forceinline__ void grid_sync_(unsigned target) {
    __syncthreads();
    if (threadIdx.x == 0) {
        __threadfence();
        atomicAdd(&g_bar, 1u);
        unsigned v;
        do {
            asm volatile("ld.global.acquire.gpu.u32 %0, [%1];" : "=r"(v) : "l"(&g_bar));
        } while (v < target);
    }
    __syncthreads();
}

// ---------------- init: zero encoder h0, reset barrier ----------------
__global__ void init_kernel(float* __restrict__ h0, int n) {
    int i = blockIdx.x * blockDim.x + threadIdx.x;
    int stride = gridDim.x * blockDim.x;
    for (; i < n; i += stride) h0[i] = 0.0f;
    if (blockIdx.x == 0 && threadIdx.x == 0) g_bar = 0u;
}

// ---------------- embedding gather (time-major) ----------------
__global__ void embed_kernel(const int* __restrict__ tokens, const float* __restrict__ emb,
                             float* __restrict__ X, int T, int toff) {
    int total4 = T * Bz * (Ez / 4);
    int i = blockIdx.x * blockDim.x + threadIdx.x;
    int stride = gridDim.x * blockDim.x;
    const int E4 = Ez / 4;
    for (; i < total4; i += stride) {
        int e4 = i % E4;
        int r  = i / E4;
        int b  = r % Bz;
        int t  = r / Bz;
        int tok = tokens[b * Sz + t + toff];
        ((float4*)X)[i] = ((const float4*)(emb + (size_t)tok * Ez))[e4];
    }
}

// ---------------- generic NT SGEMM (unchanged from R2) ----------------
__global__ __launch_bounds__(256, 2)
void sgemm_nt_kernel(const float* __restrict__ A, const float* __restrict__ W,
                     float* __restrict__ C, int M, int N, int K,
                     const float* __restrict__ bias1, const float* __restrict__ bias2, int mode) {
    __shared__ float As[16][132];
    __shared__ float Bs[16][132];

    const int n0 = blockIdx.x * 128;
    const int m0 = blockIdx.y * 128;
    const int tid = threadIdx.x;
    const int tx = tid & 15;
    const int ty = tid >> 4;
    const int lm = tid >> 2;
    const int lk4 = tid & 3;

    unsigned long long c2[8][4];
#pragma unroll
    for (int i = 0; i < 8; i++)
#pragma unroll
        for (int j = 0; j < 4; j++) c2[i][j] = 0ull;

    for (int k0 = 0; k0 < K; k0 += 16) {
#pragma unroll
        for (int r = 0; r < 2; r++) {
            int m = lm + r * 64;
            float4 v = make_float4(0.f, 0.f, 0.f, 0.f);
            int gm = m0 + m;
            if (gm < M) v = *(const float4*)(A + (size_t)gm * K + k0 + lk4 * 4);
            As[lk4 * 4 + 0][m] = v.x;
            As[lk4 * 4 + 1][m] = v.y;
            As[lk4 * 4 + 2][m] = v.z;
            As[lk4 * 4 + 3][m] = v.w;
        }
#pragma unroll
        for (int r = 0; r < 2; r++) {
            int n = lm + r * 64;
            float4 v = *(const float4*)(W + (size_t)(n0 + n) * K + k0 + lk4 * 4);
            Bs[lk4 * 4 + 0][n] = v.x;
            Bs[lk4 * 4 + 1][n] = v.y;
            Bs[lk4 * 4 + 2][n] = v.z;
            Bs[lk4 * 4 + 3][n] = v.w;
        }
        __syncthreads();

#pragma unroll
        for (int kk = 0; kk < 16; kk++) {
            float a[8];
            *(float4*)(&a[0]) = *(const float4*)(&As[kk][ty * 8]);
            *(float4*)(&a[4]) = *(const float4*)(&As[kk][ty * 8 + 4]);
            float b[8];
            *(float4*)(&b[0]) = *(const float4*)(&Bs[kk][tx * 8]);
            *(float4*)(&b[4]) = *(const float4*)(&Bs[kk][tx * 8 + 4]);
            unsigned long long b2[4];
#pragma unroll
            for (int j = 0; j < 4; j++) b2[j] = pk2(b[2 * j], b[2 * j + 1]);
#pragma unroll
            for (int i = 0; i < 8; i++) {
                unsigned long long a2 = pk2(a[i], a[i]);
#pragma unroll
                for (int j = 0; j < 4; j++) c2[i][j] = ffma2(a2, b2[j], c2[i][j]);
            }
        }
        __syncthreads();
    }

#pragma unroll
    for (int i = 0; i < 8; i++) {
        int m = m0 + ty * 8 + i;
        if (m >= M) continue;
        size_t rowbase;
        if (mode == 0) {
            rowbase = (size_t)m * N;
        } else {
            int bb = m & (Bz - 1);
            int tt = m >> 5;
            rowbase = (size_t)(bb * TDz + tt) * N;
        }
#pragma unroll
        for (int j = 0; j < 4; j++) {
            float2 v = upk2(c2[i][j]);
            int n = n0 + tx * 8 + 2 * j;
            float add0 = bias1[n], add1 = bias1[n + 1];
            if (mode == 0) { add0 += bias2[n]; add1 += bias2[n + 1]; }
            C[rowbase + n]     = v.x + add0;
            C[rowbase + n + 1] = v.y + add1;
        }
    }
}

// ---------------- persistent LSTM building blocks ----------------
__device__ __forceinline__ void load_w(const float* __restrict__ Whh, int u, int lane,
                                       unsigned long long (&w2)[4][8][2]) {
#pragma unroll
    for (int r = 0; r < 4; r++) {
        const float4* wr = (const float4*)(Whh + (size_t)(r * Hz + u) * Hz);
#pragma unroll
        for (int j = 0; j < 8; j++) {
            float4 v = wr[j * 32 + lane];
            w2[r][j][0] = pk2(v.x, v.y);
            w2[r][j][1] = pk2(v.z, v.w);
        }
    }
}

__device__ __forceinline__ void dot4(const unsigned long long (&w2)[4][8][2],
                                     const float4* __restrict__ hb, int lane,
                                     unsigned long long (&acc)[4]) {
#pragma unroll
    for (int r = 0; r < 4; r++) acc[r] = 0ull;
#pragma unroll
    for (int j = 0; j < 8; j++) {
        float4 hvj = hb[j * 32 + lane];
        unsigned long long h01 = pk2(hvj.x, hvj.y);
        unsigned long long h23 = pk2(hvj.z, hvj.w);
#pragma unroll
        for (int r = 0; r < 4; r++) {
            acc[r] = ffma2(w2[r][j][0], h01, acc[r]);
            acc[r] = ffma2(w2[r][j][1], h23, acc[r]);
        }
    }
}

// cross-lane reduction of 4 packed sums; lanes 0..3 end up holding gate 0..3
__device__ __forceinline__ float reduce4(const unsigned long long (&acc)[4], int lane) {
    float2 p0 = upk2(acc[0]); float v0 = p0.x + p0.y;
    float2 p1 = upk2(acc[1]); float v1 = p1.x + p1.y;
    float2 p2 = upk2(acc[2]); float v2 = p2.x + p2.y;
    float2 p3 = upk2(acc[3]); float v3 = p3.x + p3.y;
    v0 += __shfl_xor_sync(0xffffffffu, v0, 1);
    v1 += __shfl_xor_sync(0xffffffffu, v1, 1);
    v2 += __shfl_xor_sync(0xffffffffu, v2, 1);
    v3 += __shfl_xor_sync(0xffffffffu, v3, 1);
    float a  = (lane & 1) ? v1 : v0;
    float bb = (lane & 1) ? v3 : v2;
    a  += __shfl_xor_sync(0xffffffffu, a, 2);
    bb += __shfl_xor_sync(0xffffffffu, bb, 2);
    float m = (lane & 2) ? bb : a;
    m += __shfl_xor_sync(0xffffffffu, m, 4);
    m += __shfl_xor_sync(0xffffffffu, m, 8);
    m += __shfl_xor_sync(0xffffffffu, m, 16);
    return m;
}

// one LSTM step; returns the new cell value for this thread's (ul=tid&7, b=tid>>3)
__device__ __forceinline__ float lstm_step_p(
    const unsigned long long (&w2)[4][8][2],
    const float* __restrict__ P, const float* __restrict__ hin,
    float* __restrict__ hout, float creg,
    float* __restrict__ sgf, float* __restrict__ sPf,
    int u0, int tid, int w, int lane)
{
    // prefetch this block's P slice into smem: sPf[b*33 + g*8 + ul]
#pragma unroll
    for (int k = 0; k < 4; k++) {
        int idx = tid + k * 256;
        int b = idx >> 5, c = idx & 31;
        sPf[b * 33 + c] = P[(size_t)b * Gz + (c >> 3) * Hz + u0 + (c & 7)];
    }

    const float4* h4 = (const float4*)hin;
    unsigned long long acc[2][4];
    dot4(w2, h4, lane, acc[0]);                 // batch 0
#pragma unroll 2
    for (int b = 1; b < Bz; b++) {
        dot4(w2, h4 + b * 256, lane, acc[b & 1]);        // batch b
        float m = reduce4(acc[(b - 1) & 1], lane);       // reduce batch b-1 (overlaps)
        if (lane < 4) sgf[w * 132 + (b - 1) * 4 + lane] = m;
    }
    {
        float m = reduce4(acc[(Bz - 1) & 1], lane);
        if (lane < 4) sgf[w * 132 + (Bz - 1) * 4 + lane] = m;
    }
    __syncthreads();

    // epilogue: thread -> (ul = tid&7, b = tid>>3); coalesced hout writes
    int ul = tid & 7, b = tid >> 3;
    float gi = sgf[ul * 132 + b * 4 + 0] + sPf[b * 33 +  0 + ul];
    float gf = sgf[ul * 132 + b * 4 + 1] + sPf[b * 33 +  8 + ul];
    float gg = sgf[ul * 132 + b * 4 + 2] + sPf[b * 33 + 16 + ul];
    float go = sgf[ul * 132 + b * 4 + 3] + sPf[b * 33 + 24 + ul];
    float cc = sigm(gf) * creg + sigm(gi) * tanhf(gg);
    float hh = sigm(go) * tanhf(cc);
    hout[b * Hz + u0 + ul] = hh;
    return cc;
}

// latent head for one batch (run by blocks 0..31 between recurrences)
__device__ void latent_dev(int b, int tid,
                           const int* __restrict__ tokens, const float* __restrict__ hs,
                           const float* __restrict__ Wmu, const float* __restrict__ bmu,
                           const float* __restrict__ Wlv, const float* __restrict__ blv,
                           const float* __restrict__ eps,
                           const float* __restrict__ Wl2h, const float* __restrict__ bl2h,
                           float* __restrict__ out_mean, float* __restrict__ out_lv,
                           float* __restrict__ hd0,
                           int* __restrict__ scnt, float* __restrict__ smean,
                           float* __restrict__ slv, float* __restrict__ szv) {
    int cnt = 0;
    if (tid < Sz) cnt = (tokens[b * Sz + tid] != 0) ? 1 : 0;
    scnt[tid] = cnt;
    __syncthreads();
    for (int off = 128; off >= 1; off >>= 1) {
        if (tid < off) scnt[tid] += scnt[tid + off];
        __syncthreads();
    }
    int last = scnt[0] - 1;
    if (last < 0) last = 0;

    const float* lh = hs + (size_t)(last + 1) * Bz * Hz + (size_t)b * Hz;
    {
        int j = tid & 127;
        const float* Wr = ((tid < 128) ? Wmu : Wlv) + (size_t)j * Hz;
        float acc = 0.f;
        const float4* l4 = (const float4*)lh;
        const float4* w4 = (const float4*)Wr;
#pragma unroll 4
        for (int k = 0; k < Hz / 4; k++) {
            float4 a = l4[k];
            float4 ww = w4[k];
            acc += a.x * ww.x + a.y * ww.y + a.z * ww.z + a.w * ww.w;
        }
        if (tid < 128) smean[j] = acc + bmu[j];
        else           slv[j]   = acc + blv[j];
    }
    __syncthreads();

    if (tid < 128) {
        float m = smean[tid];
        float lv = slv[tid];
        out_mean[b * Lz + tid] = m;
        out_lv[b * Lz + tid] = lv;
        szv[tid] = m + eps[b * Lz + tid] * expf(0.5f * lv);
    }
    __syncthreads();

#pragma unroll
    for (int r = 0; r < 4; r++) {
        int u = tid + r * 256;
        float acc = bl2h[u];
        const float* wr = Wl2h + (size_t)u * Lz;
#pragma unroll 4
        for (int l = 0; l < Lz; l++) acc += szv[l] * wr[l];
        hd0[b * Hz + u] = acc;
    }
}

// ---------------- the persistent recurrence kernel ----------------
__global__ __launch_bounds__(256, 1)
void lstm_persistent(const float* __restrict__ Whh_e, const float* __restrict__ Whh_d,
                     const float* __restrict__ Pe, const float* __restrict__ Pd,
                     float* __restrict__ hse, float* __restrict__ hsd,
                     const int* __restrict__ tokens,
                     const float* __restrict__ Wmu, const float* __restrict__ bmu,
                     const float* __restrict__ Wlv, const float* __restrict__ blv,
                     const float* __restrict__ eps,
                     const float* __restrict__ Wl2h, const float* __restrict__ bl2h,
                     float* __restrict__ out_mean, float* __restrict__ out_lv) {
    const int tid = threadIdx.x;
    const int w = tid >> 5;
    const int lane = tid & 31;
    const int u0 = blockIdx.x * 8;
    const int u = u0 + w;

    __shared__ float sgf[8 * 132];
    __shared__ float sPf[32 * 33];
    __shared__ int   scnt[256];
    __shared__ float smean[128], slvs[128], szv[128];

    unsigned long long w2[4][8][2];
    load_w(Whh_e, u, lane, w2);

    float creg = 0.f;
    unsigned epoch = 0;

    // encoder: 128 steps
    for (int t = 0; t < Sz; t++) {
        creg = lstm_step_p(w2, Pe + (size_t)t * Bz * Gz,
                           hse + (size_t)t * Bz * Hz,
                           hse + (size_t)(t + 1) * Bz * Hz,
                           creg, sgf, sPf, u0, tid, w, lane);
        epoch++;
        grid_sync_(epoch * NBLK);
    }

    // swap to decoder weights; blocks 0..31 compute the latent head
    load_w(Whh_d, u, lane, w2);
    if (blockIdx.x < 32) {
        latent_dev(blockIdx.x, tid, tokens, hse, Wmu, bmu, Wlv, blv, eps,
                   Wl2h, bl2h, out_mean, out_lv, hsd /*slot 0*/,
                   scnt, smean, slvs, szv);
    }
    epoch++;
    grid_sync_(epoch * NBLK);

    creg = 0.f;   // decoder c0 = 0
    for (int t = 0; t < TDz; t++) {
        creg = lstm_step_p(w2, Pd + (size_t)t * Bz * Gz,
                           hsd + (size_t)t * Bz * Hz,
                           hsd + (size_t)(t + 1) * Bz * Hz,
                           creg, sgf, sPf, u0, tid, w, lane);
        if (t < TDz - 1) {
            epoch++;
            grid_sync_(epoch * NBLK);
        }
    }
}

// ---------------- launch ----------------
extern "C" void kernel_launch(void* const* d_in, const int* in_sizes, int n_in,
                              void* d_out, int out_size) {
    const int*   tokens  = (const int*)d_in[0];
    const float* emb_enc = (const float*)d_in[1];
    const float* Wih_e   = (const float*)d_in[2];
    const float* Whh_e   = (const float*)d_in[3];
    const float* bih_e   = (const float*)d_in[4];
    const float* bhh_e   = (const float*)d_in[5];
    const float* W_mu    = (const float*)d_in[6];
    const float* b_mu    = (const float*)d_in[7];
    const float* W_lv    = (const float*)d_in[8];
    const float* b_lv    = (const float*)d_in[9];
    const float* emb_dec = (const float*)d_in[10];
    const float* W_l2h   = (const float*)d_in[11];
    const float* b_l2h   = (const float*)d_in[12];
    const float* Wih_d   = (const float*)d_in[13];
    const float* Whh_d   = (const float*)d_in[14];
    const float* bih_d   = (const float*)d_in[15];
    const float* bhh_d   = (const float*)d_in[16];
    const float* W_out   = (const float*)d_in[17];
    const float* b_out   = (const float*)d_in[18];
    const float* epsv    = (const float*)d_in[19];

    float* out = (float*)d_out;
    const size_t LOGITS = (size_t)Bz * TDz * Vz;
    float* out_logits = out;
    float* out_mean   = out + LOGITS;
    float* out_lv     = out + LOGITS + (size_t)Bz * Lz;

    float *p_Xe, *p_Pe, *p_hse, *p_Xd, *p_Pd, *p_hsd;
    cudaGetSymbolAddress((void**)&p_Xe,  g_Xe);
    cudaGetSymbolAddress((void**)&p_Pe,  g_Pe);
    cudaGetSymbolAddress((void**)&p_hse, g_hse);
    cudaGetSymbolAddress((void**)&p_Xd,  g_Xd);
    cudaGetSymbolAddress((void**)&p_Pd,  g_Pd);
    cudaGetSymbolAddress((void**)&p_hsd, g_hsd);

    // 1) zero encoder h0 slot; reset grid barrier
    init_kernel<<<64, 256>>>(p_hse, Bz * Hz);

    // 2) embeddings
    embed_kernel<<<2048, 256>>>(tokens, emb_enc, p_Xe, Sz, 0);
    embed_kernel<<<2048, 256>>>(tokens, emb_dec, p_Xd, TDz, 1);

    // 3) input projections (hoisted out of the recurrences)
    {
        dim3 grid(Gz / 128, (Sz * Bz + 127) / 128);
        sgemm_nt_kernel<<<grid, 256>>>(p_Xe, Wih_e, p_Pe, Sz * Bz, Gz, Ez, bih_e, bhh_e, 0);
    }
    {
        dim3 grid(Gz / 128, (TDz * Bz + 127) / 128);
        sgemm_nt_kernel<<<grid, 256>>>(p_Xd, Wih_d, p_Pd, TDz * Bz, Gz, Ez, bih_d, bhh_d, 0);
    }

    // 4+5+6) both recurrences + latent head in ONE persistent kernel
    lstm_persistent<<<NBLK, 256>>>(Whh_e, Whh_d, p_Pe, p_Pd, p_hse, p_hsd,
                                   tokens, W_mu, b_mu, W_lv, b_lv, epsv,
                                   W_l2h, b_l2h, out_mean, out_lv);

    // 7) output projection -> logits
    {
        dim3 grid(Vz / 128, (TDz * Bz + 127) / 128);
        sgemm_nt_kernel<<<grid, 256>>>(p_hsd + (size_t)Bz * Hz, W_out, out_logits,
                                       TDz * Bz, Vz, Hz, b_out, b_out, 1);
    }
}

// round 5
// speedup vs baseline: 6.2696x; 1.5344x over previous
#include <cuda_runtime.h>
#include <cuda_bf16.h>
#include <math.h>
#include <stdint.h>

// Problem dims
#define Bz 32
#define Sz 128
#define Ez 512
#define Hz 1024
#define Gz 4096   // 4*H
#define Lz 128
#define Vz 32000
#define TDz 126   // S-2
#define NBLK 128  // persistent grid size

// ---------------- scratch (device globals; no runtime allocation) ----------------
__device__ float g_Xe[Sz * Bz * Ez];
__device__ float g_Pe[(size_t)Sz * Bz * Gz];
__device__ float g_hse[(Sz + 1) * Bz * Hz];
__device__ float g_Xd[TDz * Bz * Ez];
__device__ float g_Pd[(size_t)TDz * Bz * Gz];
__device__ float g_hsd[(TDz + 1) * Bz * Hz];
__device__ unsigned g_bar;
// bf16 split buffers for the tensor-core logits GEMM
__device__ __nv_bfloat16 g_Whi[(size_t)Vz * Hz];
__device__ __nv_bfloat16 g_Wlo[(size_t)Vz * Hz];
__device__ __nv_bfloat16 g_Ahi[4096 * Hz];
__device__ __nv_bfloat16 g_Alo[4096 * Hz];

// ---------------- f32x2 helpers ----------------
__device__ __forceinline__ unsigned long long pk2(float x, float y) {
    unsigned long long r;
    asm("mov.b64 %0, {%1,%2};" : "=l"(r) : "f"(x), "f"(y));
    return r;
}
__device__ __forceinline__ float2 upk2(unsigned long long v) {
    float2 r;
    asm("mov.b64 {%0,%1}, %2;" : "=f"(r.x), "=f"(r.y) : "l"(v));
    return r;
}
__device__ __forceinline__ unsigned long long ffma2(unsigned long long a, unsigned long long b,
                                                    unsigned long long c) {
    unsigned long long d;
    asm("fma.rn.f32x2 %0, %1, %2, %3;" : "=l"(d) : "l"(a), "l"(b), "l"(c));
    return d;
}
__device__ __forceinline__ float sigm(float x) { return 1.0f / (1.0f + expf(-x)); }

__device__ __forceinline__ uint32_t smem_u32(const void* p) {
    uint32_t a;
    asm("{ .reg .u64 t; cvta.to.shared.u64 t, %1; cvt.u32.u64 %0, t; }" : "=r"(a) : "l"(p));
    return a;
}

// ---------------- mma.sync helpers (compute_103-safe, sm_80-era PTX) ----------------
#define LDSM4(d, addr) \
    asm volatile("ldmatrix.sync.aligned.m8n8.x4.shared.b16 {%0,%1,%2,%3}, [%4];" \
        : "=r"((d)[0]), "=r"((d)[1]), "=r"((d)[2]), "=r"((d)[3]) : "r"(addr))

#define MMA16816(c, a, b) \
    asm volatile("mma.sync.aligned.m16n8k16.row.col.f32.bf16.bf16.f32 " \
        "{%0,%1,%2,%3}, {%4,%5,%6,%7}, {%8,%9}, {%0,%1,%2,%3};" \
        : "+f"((c)[0]), "+f"((c)[1]), "+f"((c)[2]), "+f"((c)[3]) \
        : "r"((a)[0]), "r"((a)[1]), "r"((a)[2]), "r"((a)[3]), "r"((b)[0]), "r"((b)[1]))

// ---------------- grid barrier ----------------
__device__ __forceinline__ void grid_sync_(unsigned target) {
    __syncthreads();
    if (threadIdx.x == 0) {
        __threadfence();
        atomicAdd(&g_bar, 1u);
        unsigned v;
        do {
            asm volatile("ld.global.acquire.gpu.u32 %0, [%1];" : "=r"(v) : "l"(&g_bar));
        } while (v < target);
    }
    __syncthreads();
}

// ---------------- init ----------------
__global__ void init_kernel(float* __restrict__ h0, int n) {
    int i = blockIdx.x * blockDim.x + threadIdx.x;
    int stride = gridDim.x * blockDim.x;
    for (; i < n; i += stride) h0[i] = 0.0f;
    if (blockIdx.x == 0 && threadIdx.x == 0) g_bar = 0u;
}

// ---------------- embedding gather ----------------
__global__ void embed_kernel(const int* __restrict__ tokens, const float* __restrict__ emb,
                             float* __restrict__ X, int T, int toff) {
    int total4 = T * Bz * (Ez / 4);
    int i = blockIdx.x * blockDim.x + threadIdx.x;
    int stride = gridDim.x * blockDim.x;
    const int E4 = Ez / 4;
    for (; i < total4; i += stride) {
        int e4 = i % E4;
        int r  = i / E4;
        int b  = r % Bz;
        int t  = r / Bz;
        int tok = tokens[b * Sz + t + toff];
        ((float4*)X)[i] = ((const float4*)(emb + (size_t)tok * Ez))[e4];
    }
}

// ---------------- bf16 split conversions ----------------
__global__ void convert_w_kernel(const float* __restrict__ W, __nv_bfloat16* __restrict__ hi,
                                 __nv_bfloat16* __restrict__ lo, int n4) {
    int i = blockIdx.x * blockDim.x + threadIdx.x;
    int stride = gridDim.x * blockDim.x;
    for (; i < n4; i += stride) {
        float4 v = ((const float4*)W)[i];
        __nv_bfloat16 h0 = __float2bfloat16(v.x);
        __nv_bfloat16 h1 = __float2bfloat16(v.y);
        __nv_bfloat16 h2 = __float2bfloat16(v.z);
        __nv_bfloat16 h3 = __float2bfloat16(v.w);
        __nv_bfloat162 ha; ha.x = h0; ha.y = h1;
        __nv_bfloat162 hb; hb.x = h2; hb.y = h3;
        ((__nv_bfloat162*)hi)[i * 2]     = ha;
        ((__nv_bfloat162*)hi)[i * 2 + 1] = hb;
        __nv_bfloat162 la, lb;
        la.x = __float2bfloat16(v.x - __bfloat162float(h0));
        la.y = __float2bfloat16(v.y - __bfloat162float(h1));
        lb.x = __float2bfloat16(v.z - __bfloat162float(h2));
        lb.y = __float2bfloat16(v.w - __bfloat162float(h3));
        ((__nv_bfloat162*)lo)[i * 2]     = la;
        ((__nv_bfloat162*)lo)[i * 2 + 1] = lb;
    }
}

// A row m (= t*Bz+b) = hsd[(m+32)*Hz + k]; rows >= 4032 zero-padded
__global__ void convert_a_kernel(const float* __restrict__ hsd, __nv_bfloat16* __restrict__ hi,
                                 __nv_bfloat16* __restrict__ lo) {
    int n4 = 4096 * Hz / 4;
    int i = blockIdx.x * blockDim.x + threadIdx.x;
    int stride = gridDim.x * blockDim.x;
    for (; i < n4; i += stride) {
        int e = i * 4;
        int m = e >> 10;
        int k = e & 1023;
        float4 v = make_float4(0.f, 0.f, 0.f, 0.f);
        if (m < TDz * Bz) v = *(const float4*)(hsd + (size_t)(m + 32) * Hz + k);
        __nv_bfloat16 h0 = __float2bfloat16(v.x);
        __nv_bfloat16 h1 = __float2bfloat16(v.y);
        __nv_bfloat16 h2 = __float2bfloat16(v.z);
        __nv_bfloat16 h3 = __float2bfloat16(v.w);
        __nv_bfloat162 ha; ha.x = h0; ha.y = h1;
        __nv_bfloat162 hb; hb.x = h2; hb.y = h3;
        ((__nv_bfloat162*)hi)[i * 2]     = ha;
        ((__nv_bfloat162*)hi)[i * 2 + 1] = hb;
        __nv_bfloat162 la, lb;
        la.x = __float2bfloat16(v.x - __bfloat162float(h0));
        la.y = __float2bfloat16(v.y - __bfloat162float(h1));
        lb.x = __float2bfloat16(v.z - __bfloat162float(h2));
        lb.y = __float2bfloat16(v.w - __bfloat162float(h3));
        ((__nv_bfloat162*)lo)[i * 2]     = la;
        ((__nv_bfloat162*)lo)[i * 2 + 1] = lb;
    }
}

// ---------------- mma.sync logits GEMM ----------------
// C[4032 x 32000] = A[4032 x 1024] @ W^T, bf16 3-split, fp32 accum.
// Tile 128x128x32, 256 threads (warp grid 2m x 4n, warp tile 64x32).
// smem rows padded to 40 bf16 (80B) -> conflict-free ldmatrix.
#define SSTR   80
#define SA_HI  0
#define SA_LO  10240
#define SB_HI  20480
#define SB_LO  30720
#define STAGE  40960
#define SBIAS  (2 * STAGE)
#define SMEM_MMA (2 * STAGE + 512)

__global__ __launch_bounds__(256, 1)
void mma_logits_kernel(const __nv_bfloat16* __restrict__ Ahi, const __nv_bfloat16* __restrict__ Alo,
                       const __nv_bfloat16* __restrict__ Whi, const __nv_bfloat16* __restrict__ Wlo,
                       const float* __restrict__ bias, float* __restrict__ out) {
    extern __shared__ char smem[];
    const uint32_t sbase = smem_u32(smem);
    const int tid = threadIdx.x;
    const int w = tid >> 5, lane = tid & 31;
    const int mtile = blockIdx.x;       // 0..31
    const int ntile = blockIdx.y;       // 0..249
    const int wm = (w & 1) * 64;
    const int wn = (w >> 1) * 32;

    if (tid < 128) ((float*)(smem + SBIAS))[tid] = bias[ntile * 128 + tid];

    // ---- G2S addressing: thread handles rows (tid>>2) and (tid>>2)+64, k-chunk (tid&3)*8 ----
    const int row = tid >> 2;
    const int ko  = (tid & 3) * 8;
    const __nv_bfloat16* gA0h = Ahi + (size_t)(mtile * 128 + row) * Hz + ko;
    const __nv_bfloat16* gA1h = Ahi + (size_t)(mtile * 128 + row + 64) * Hz + ko;
    const __nv_bfloat16* gA0l = Alo + (size_t)(mtile * 128 + row) * Hz + ko;
    const __nv_bfloat16* gA1l = Alo + (size_t)(mtile * 128 + row + 64) * Hz + ko;
    const __nv_bfloat16* gB0h = Whi + (size_t)(ntile * 128 + row) * Hz + ko;
    const __nv_bfloat16* gB1h = Whi + (size_t)(ntile * 128 + row + 64) * Hz + ko;
    const __nv_bfloat16* gB0l = Wlo + (size_t)(ntile * 128 + row) * Hz + ko;
    const __nv_bfloat16* gB1l = Wlo + (size_t)(ntile * 128 + row + 64) * Hz + ko;
    const uint32_t s0 = row * SSTR + ko * 2;
    const uint32_t s1 = (row + 64) * SSTR + ko * 2;

    // ---- ldmatrix lane bases ----
    // A: lanes 0-15 -> rows 0..15 @k, lanes 16-31 -> rows 0..15 @k+8
    const uint32_t aLane = (uint32_t)(wm + (lane & 15)) * SSTR + (uint32_t)(lane >> 4) * 16;
    // B x4 covers 2 n-atoms: group(lane>>3): {n0-7,k},{n0-7,k+8},{n8-15,k},{n8-15,k+8}
    const uint32_t bLane = (uint32_t)(wn + (lane & 7) + ((lane >> 4) << 3)) * SSTR +
                           (uint32_t)((lane >> 3) & 1) * 16;

    float acc[4][4][4];
#pragma unroll
    for (int i = 0; i < 4; i++)
#pragma unroll
        for (int j = 0; j < 4; j++)
#pragma unroll
            for (int q = 0; q < 4; q++) acc[i][j][q] = 0.f;

    // ---- prologue: stage 0 ----
    {
        char* st = smem;
        *(uint4*)(st + SA_HI + s0) = *(const uint4*)gA0h;
        *(uint4*)(st + SA_HI + s1) = *(const uint4*)gA1h;
        *(uint4*)(st + SA_LO + s0) = *(const uint4*)gA0l;
        *(uint4*)(st + SA_LO + s1) = *(const uint4*)gA1l;
        *(uint4*)(st + SB_HI + s0) = *(const uint4*)gB0h;
        *(uint4*)(st + SB_HI + s1) = *(const uint4*)gB1h;
        *(uint4*)(st + SB_LO + s0) = *(const uint4*)gB0l;
        *(uint4*)(st + SB_LO + s1) = *(const uint4*)gB1l;
    }
    __syncthreads();

    for (int kt = 0; kt < 32; kt++) {
        const uint32_t stg = (uint32_t)(kt & 1) * STAGE;

        // prefetch kt+1 into registers
        uint4 r0, r1, r2, r3, r4, r5, r6, r7;
        if (kt < 31) {
            const int go = (kt + 1) * 32 / 8;      // uint4 index advance
            r0 = ((const uint4*)gA0h)[go]; r1 = ((const uint4*)gA1h)[go];
            r2 = ((const uint4*)gA0l)[go]; r3 = ((const uint4*)gA1l)[go];
            r4 = ((const uint4*)gB0h)[go]; r5 = ((const uint4*)gB1h)[go];
            r6 = ((const uint4*)gB0l)[go]; r7 = ((const uint4*)gB1l)[go];
        }

        // compute on current stage
#pragma unroll
        for (int ks = 0; ks < 2; ks++) {
            const uint32_t kofs = (uint32_t)ks * 32;   // 16 bf16 = 32 bytes
            uint32_t aH[4][4], aL[4][4];
#pragma unroll
            for (int ma = 0; ma < 4; ma++) {
                uint32_t ad = sbase + stg + aLane + (uint32_t)ma * (16 * SSTR) + kofs;
                LDSM4(aH[ma], ad + SA_HI);
                LDSM4(aL[ma], ad + SA_LO);
            }
            uint32_t bH[4][2], bL[4][2];
#pragma unroll
            for (int nb2 = 0; nb2 < 2; nb2++) {
                uint32_t bd = sbase + stg + bLane + (uint32_t)nb2 * (16 * SSTR) + kofs;
                uint32_t t[4];
                LDSM4(t, bd + SB_HI);
                bH[nb2 * 2][0] = t[0]; bH[nb2 * 2][1] = t[1];
                bH[nb2 * 2 + 1][0] = t[2]; bH[nb2 * 2 + 1][1] = t[3];
                LDSM4(t, bd + SB_LO);
                bL[nb2 * 2][0] = t[0]; bL[nb2 * 2][1] = t[1];
                bL[nb2 * 2 + 1][0] = t[2]; bL[nb2 * 2 + 1][1] = t[3];
            }
#pragma unroll
            for (int ma = 0; ma < 4; ma++)
#pragma unroll
                for (int nb = 0; nb < 4; nb++) {
                    MMA16816(acc[ma][nb], aH[ma], bH[nb]);
                    MMA16816(acc[ma][nb], aH[ma], bL[nb]);
                    MMA16816(acc[ma][nb], aL[ma], bH[nb]);
                }
        }

        // store prefetched data into the other stage
        if (kt < 31) {
            char* st = smem + ((kt + 1) & 1) * STAGE;
            *(uint4*)(st + SA_HI + s0) = r0;
            *(uint4*)(st + SA_HI + s1) = r1;
            *(uint4*)(st + SA_LO + s0) = r2;
            *(uint4*)(st + SA_LO + s1) = r3;
            *(uint4*)(st + SB_HI + s0) = r4;
            *(uint4*)(st + SB_HI + s1) = r5;
            *(uint4*)(st + SB_LO + s0) = r6;
            *(uint4*)(st + SB_LO + s1) = r7;
        }
        __syncthreads();
    }

    // ---- epilogue: bias add + (t,b)->(b,t) remap ----
    const float* sbias = (const float*)(smem + SBIAS);
#pragma unroll
    for (int ma = 0; ma < 4; ma++) {
        const int m0 = mtile * 128 + wm + ma * 16 + (lane >> 2);
#pragma unroll
        for (int nb = 0; nb < 4; nb++) {
            const int cl = wn + nb * 8 + (lane & 3) * 2;
            const float b0v = sbias[cl], b1v = sbias[cl + 1];
            const size_t col = (size_t)(ntile * 128 + cl);
            if (m0 < TDz * Bz) {
                int orow = (m0 & 31) * TDz + (m0 >> 5);
                float2 v;
                v.x = acc[ma][nb][0] + b0v;
                v.y = acc[ma][nb][1] + b1v;
                *(float2*)(out + (size_t)orow * Vz + col) = v;
            }
            const int m1 = m0 + 8;
            if (m1 < TDz * Bz) {
                int orow = (m1 & 31) * TDz + (m1 >> 5);
                float2 v;
                v.x = acc[ma][nb][2] + b0v;
                v.y = acc[ma][nb][3] + b1v;
                *(float2*)(out + (size_t)orow * Vz + col) = v;
            }
        }
    }
}

// ---------------- generic NT SGEMM (input projections) ----------------
__global__ __launch_bounds__(256, 2)
void sgemm_nt_kernel(const float* __restrict__ A, const float* __restrict__ W,
                     float* __restrict__ C, int M, int N, int K,
                     const float* __restrict__ bias1, const float* __restrict__ bias2) {
    __shared__ float As[16][132];
    __shared__ float Bs[16][132];

    const int n0 = blockIdx.x * 128;
    const int m0 = blockIdx.y * 128;
    const int tid = threadIdx.x;
    const int tx = tid & 15;
    const int ty = tid >> 4;
    const int lm = tid >> 2;
    const int lk4 = tid & 3;

    unsigned long long c2[8][4];
#pragma unroll
    for (int i = 0; i < 8; i++)
#pragma unroll
        for (int j = 0; j < 4; j++) c2[i][j] = 0ull;

    for (int k0 = 0; k0 < K; k0 += 16) {
#pragma unroll
        for (int r = 0; r < 2; r++) {
            int m = lm + r * 64;
            float4 v = make_float4(0.f, 0.f, 0.f, 0.f);
            int gm = m0 + m;
            if (gm < M) v = *(const float4*)(A + (size_t)gm * K + k0 + lk4 * 4);
            As[lk4 * 4 + 0][m] = v.x;
            As[lk4 * 4 + 1][m] = v.y;
            As[lk4 * 4 + 2][m] = v.z;
            As[lk4 * 4 + 3][m] = v.w;
        }
#pragma unroll
        for (int r = 0; r < 2; r++) {
            int n = lm + r * 64;
            float4 v = *(const float4*)(W + (size_t)(n0 + n) * K + k0 + lk4 * 4);
            Bs[lk4 * 4 + 0][n] = v.x;
            Bs[lk4 * 4 + 1][n] = v.y;
            Bs[lk4 * 4 + 2][n] = v.z;
            Bs[lk4 * 4 + 3][n] = v.w;
        }
        __syncthreads();

#pragma unroll
        for (int kk = 0; kk < 16; kk++) {
            float a[8];
            *(float4*)(&a[0]) = *(const float4*)(&As[kk][ty * 8]);
            *(float4*)(&a[4]) = *(const float4*)(&As[kk][ty * 8 + 4]);
            float b[8];
            *(float4*)(&b[0]) = *(const float4*)(&Bs[kk][tx * 8]);
            *(float4*)(&b[4]) = *(const float4*)(&Bs[kk][tx * 8 + 4]);
            unsigned long long b2[4];
#pragma unroll
            for (int j = 0; j < 4; j++) b2[j] = pk2(b[2 * j], b[2 * j + 1]);
#pragma unroll
            for (int i = 0; i < 8; i++) {
                unsigned long long a2 = pk2(a[i], a[i]);
#pragma unroll
                for (int j = 0; j < 4; j++) c2[i][j] = ffma2(a2, b2[j], c2[i][j]);
            }
        }
        __syncthreads();
    }

#pragma unroll
    for (int i = 0; i < 8; i++) {
        int m = m0 + ty * 8 + i;
        if (m >= M) continue;
        size_t rowbase = (size_t)m * N;
#pragma unroll
        for (int j = 0; j < 4; j++) {
            float2 v = upk2(c2[i][j]);
            int n = n0 + tx * 8 + 2 * j;
            C[rowbase + n]     = v.x + bias1[n] + bias2[n];
            C[rowbase + n + 1] = v.y + bias1[n + 1] + bias2[n + 1];
        }
    }
}

// ---------------- persistent LSTM building blocks ----------------
__device__ __forceinline__ void load_w(const float* __restrict__ Whh, int u, int lane,
                                       unsigned long long (&w2)[4][8][2]) {
#pragma unroll
    for (int r = 0; r < 4; r++) {
        const float4* wr = (const float4*)(Whh + (size_t)(r * Hz + u) * Hz);
#pragma unroll
        for (int j = 0; j < 8; j++) {
            float4 v = wr[j * 32 + lane];
            w2[r][j][0] = pk2(v.x, v.y);
            w2[r][j][1] = pk2(v.z, v.w);
        }
    }
}

__device__ __forceinline__ void dot4(const unsigned long long (&w2)[4][8][2],
                                     const float4* __restrict__ hb, int lane,
                                     unsigned long long (&acc)[4]) {
#pragma unroll
    for (int r = 0; r < 4; r++) acc[r] = 0ull;
#pragma unroll
    for (int j = 0; j < 8; j++) {
        float4 hvj = hb[j * 32 + lane];
        unsigned long long h01 = pk2(hvj.x, hvj.y);
        unsigned long long h23 = pk2(hvj.z, hvj.w);
#pragma unroll
        for (int r = 0; r < 4; r++) {
            acc[r] = ffma2(w2[r][j][0], h01, acc[r]);
            acc[r] = ffma2(w2[r][j][1], h23, acc[r]);
        }
    }
}

__device__ __forceinline__ float reduce4(const unsigned long long (&acc)[4], int lane) {
    float2 p0 = upk2(acc[0]); float v0 = p0.x + p0.y;
    float2 p1 = upk2(acc[1]); float v1 = p1.x + p1.y;
    float2 p2 = upk2(acc[2]); float v2 = p2.x + p2.y;
    float2 p3 = upk2(acc[3]); float v3 = p3.x + p3.y;
    v0 += __shfl_xor_sync(0xffffffffu, v0, 1);
    v1 += __shfl_xor_sync(0xffffffffu, v1, 1);
    v2 += __shfl_xor_sync(0xffffffffu, v2, 1);
    v3 += __shfl_xor_sync(0xffffffffu, v3, 1);
    float a  = (lane & 1) ? v1 : v0;
    float bb = (lane & 1) ? v3 : v2;
    a  += __shfl_xor_sync(0xffffffffu, a, 2);
    bb += __shfl_xor_sync(0xffffffffu, bb, 2);
    float m = (lane & 2) ? bb : a;
    m += __shfl_xor_sync(0xffffffffu, m, 4);
    m += __shfl_xor_sync(0xffffffffu, m, 8);
    m += __shfl_xor_sync(0xffffffffu, m, 16);
    return m;
}

__device__ __forceinline__ float lstm_step_p(
    const unsigned long long (&w2)[4][8][2],
    const float* __restrict__ P, const float* __restrict__ hin,
    float* __restrict__ hout, float creg,
    float* __restrict__ sgf, float* __restrict__ sPf,
    int u0, int tid, int w, int lane)
{
#pragma unroll
    for (int k = 0; k < 4; k++) {
        int idx = tid + k * 256;
        int b = idx >> 5, c = idx & 31;
        sPf[b * 33 + c] = P[(size_t)b * Gz + (c >> 3) * Hz + u0 + (c & 7)];
    }

    const float4* h4 = (const float4*)hin;
    unsigned long long acc[2][4];
    dot4(w2, h4, lane, acc[0]);
#pragma unroll 2
    for (int b = 1; b < Bz; b++) {
        dot4(w2, h4 + b * 256, lane, acc[b & 1]);
        float m = reduce4(acc[(b - 1) & 1], lane);
        if (lane < 4) sgf[w * 132 + (b - 1) * 4 + lane] = m;
    }
    {
        float m = reduce4(acc[(Bz - 1) & 1], lane);
        if (lane < 4) sgf[w * 132 + (Bz - 1) * 4 + lane] = m;
    }
    __syncthreads();

    int ul = tid & 7, b = tid >> 3;
    float gi = sgf[ul * 132 + b * 4 + 0] + sPf[b * 33 +  0 + ul];
    float gf = sgf[ul * 132 + b * 4 + 1] + sPf[b * 33 +  8 + ul];
    float gg = sgf[ul * 132 + b * 4 + 2] + sPf[b * 33 + 16 + ul];
    float go = sgf[ul * 132 + b * 4 + 3] + sPf[b * 33 + 24 + ul];
    float cc = sigm(gf) * creg + sigm(gi) * tanhf(gg);
    float hh = sigm(go) * tanhf(cc);
    hout[b * Hz + u0 + ul] = hh;
    return cc;
}

__device__ void latent_dev(int b, int tid,
                           const int* __restrict__ tokens, const float* __restrict__ hs,
                           const float* __restrict__ Wmu, const float* __restrict__ bmu,
                           const float* __restrict__ Wlv, const float* __restrict__ blv,
                           const float* __restrict__ eps,
                           const float* __restrict__ Wl2h, const float* __restrict__ bl2h,
                           float* __restrict__ out_mean, float* __restrict__ out_lv,
                           float* __restrict__ hd0,
                           int* __restrict__ scnt, float* __restrict__ smean,
                           float* __restrict__ slv, float* __restrict__ szv) {
    int cnt = 0;
    if (tid < Sz) cnt = (tokens[b * Sz + tid] != 0) ? 1 : 0;
    scnt[tid] = cnt;
    __syncthreads();
    for (int off = 128; off >= 1; off >>= 1) {
        if (tid < off) scnt[tid] += scnt[tid + off];
        __syncthreads();
    }
    int last = scnt[0] - 1;
    if (last < 0) last = 0;

    const float* lh = hs + (size_t)(last + 1) * Bz * Hz + (size_t)b * Hz;
    {
        int j = tid & 127;
        const float* Wr = ((tid < 128) ? Wmu : Wlv) + (size_t)j * Hz;
        float acc = 0.f;
        const float4* l4 = (const float4*)lh;
        const float4* w4 = (const float4*)Wr;
#pragma unroll 4
        for (int k = 0; k < Hz / 4; k++) {
            float4 a = l4[k];
            float4 ww = w4[k];
            acc += a.x * ww.x + a.y * ww.y + a.z * ww.z + a.w * ww.w;
        }
        if (tid < 128) smean[j] = acc + bmu[j];
        else           slv[j]   = acc + blv[j];
    }
    __syncthreads();

    if (tid < 128) {
        float m = smean[tid];
        float lv = slv[tid];
        out_mean[b * Lz + tid] = m;
        out_lv[b * Lz + tid] = lv;
        szv[tid] = m + eps[b * Lz + tid] * expf(0.5f * lv);
    }
    __syncthreads();

#pragma unroll
    for (int r = 0; r < 4; r++) {
        int u = tid + r * 256;
        float acc = bl2h[u];
        const float* wr = Wl2h + (size_t)u * Lz;
#pragma unroll 4
        for (int l = 0; l < Lz; l++) acc += szv[l] * wr[l];
        hd0[b * Hz + u] = acc;
    }
}

__global__ __launch_bounds__(256, 1)
void lstm_persistent(const float* __restrict__ Whh_e, const float* __restrict__ Whh_d,
                     const float* __restrict__ Pe, const float* __restrict__ Pd,
                     float* __restrict__ hse, float* __restrict__ hsd,
                     const int* __restrict__ tokens,
                     const float* __restrict__ Wmu, const float* __restrict__ bmu,
                     const float* __restrict__ Wlv, const float* __restrict__ blv,
                     const float* __restrict__ eps,
                     const float* __restrict__ Wl2h, const float* __restrict__ bl2h,
                     float* __restrict__ out_mean, float* __restrict__ out_lv) {
    const int tid = threadIdx.x;
    const int w = tid >> 5;
    const int lane = tid & 31;
    const int u0 = blockIdx.x * 8;
    const int u = u0 + w;

    __shared__ float sgf[8 * 132];
    __shared__ float sPf[32 * 33];
    __shared__ int   scnt[256];
    __shared__ float smean[128], slvs[128], szv[128];

    unsigned long long w2[4][8][2];
    load_w(Whh_e, u, lane, w2);

    float creg = 0.f;
    unsigned epoch = 0;

    for (int t = 0; t < Sz; t++) {
        creg = lstm_step_p(w2, Pe + (size_t)t * Bz * Gz,
                           hse + (size_t)t * Bz * Hz,
                           hse + (size_t)(t + 1) * Bz * Hz,
                           creg, sgf, sPf, u0, tid, w, lane);
        epoch++;
        grid_sync_(epoch * NBLK);
    }

    load_w(Whh_d, u, lane, w2);
    if (blockIdx.x < 32) {
        latent_dev(blockIdx.x, tid, tokens, hse, Wmu, bmu, Wlv, blv, eps,
                   Wl2h, bl2h, out_mean, out_lv, hsd,
                   scnt, smean, slvs, szv);
    }
    epoch++;
    grid_sync_(epoch * NBLK);

    creg = 0.f;
    for (int t = 0; t < TDz; t++) {
        creg = lstm_step_p(w2, Pd + (size_t)t * Bz * Gz,
                           hsd + (size_t)t * Bz * Hz,
                           hsd + (size_t)(t + 1) * Bz * Hz,
                           creg, sgf, sPf, u0, tid, w, lane);
        if (t < TDz - 1) {
            epoch++;
            grid_sync_(epoch * NBLK);
        }
    }
}

// ---------------- launch ----------------
extern "C" void kernel_launch(void* const* d_in, const int* in_sizes, int n_in,
                              void* d_out, int out_size) {
    const int*   tokens  = (const int*)d_in[0];
    const float* emb_enc = (const float*)d_in[1];
    const float* Wih_e   = (const float*)d_in[2];
    const float* Whh_e   = (const float*)d_in[3];
    const float* bih_e   = (const float*)d_in[4];
    const float* bhh_e   = (const float*)d_in[5];
    const float* W_mu    = (const float*)d_in[6];
    const float* b_mu    = (const float*)d_in[7];
    const float* W_lv    = (const float*)d_in[8];
    const float* b_lv    = (const float*)d_in[9];
    const float* emb_dec = (const float*)d_in[10];
    const float* W_l2h   = (const float*)d_in[11];
    const float* b_l2h   = (const float*)d_in[12];
    const float* Wih_d   = (const float*)d_in[13];
    const float* Whh_d   = (const float*)d_in[14];
    const float* bih_d   = (const float*)d_in[15];
    const float* bhh_d   = (const float*)d_in[16];
    const float* W_out   = (const float*)d_in[17];
    const float* b_out   = (const float*)d_in[18];
    const float* epsv    = (const float*)d_in[19];

    float* out = (float*)d_out;
    const size_t LOGITS = (size_t)Bz * TDz * Vz;
    float* out_logits = out;
    float* out_mean   = out + LOGITS;
    float* out_lv     = out + LOGITS + (size_t)Bz * Lz;

    float *p_Xe, *p_Pe, *p_hse, *p_Xd, *p_Pd, *p_hsd;
    __nv_bfloat16 *p_Whi, *p_Wlo, *p_Ahi, *p_Alo;
    cudaGetSymbolAddress((void**)&p_Xe,  g_Xe);
    cudaGetSymbolAddress((void**)&p_Pe,  g_Pe);
    cudaGetSymbolAddress((void**)&p_hse, g_hse);
    cudaGetSymbolAddress((void**)&p_Xd,  g_Xd);
    cudaGetSymbolAddress((void**)&p_Pd,  g_Pd);
    cudaGetSymbolAddress((void**)&p_hsd, g_hsd);
    cudaGetSymbolAddress((void**)&p_Whi, g_Whi);
    cudaGetSymbolAddress((void**)&p_Wlo, g_Wlo);
    cudaGetSymbolAddress((void**)&p_Ahi, g_Ahi);
    cudaGetSymbolAddress((void**)&p_Alo, g_Alo);

    // 1) zero encoder h0 slot; reset grid barrier
    init_kernel<<<64, 256>>>(p_hse, Bz * Hz);

    // 2) embeddings
    embed_kernel<<<2048, 256>>>(tokens, emb_enc, p_Xe, Sz, 0);
    embed_kernel<<<2048, 256>>>(tokens, emb_dec, p_Xd, TDz, 1);

    // 3) input projections
    {
        dim3 grid(Gz / 128, (Sz * Bz + 127) / 128);
        sgemm_nt_kernel<<<grid, 256>>>(p_Xe, Wih_e, p_Pe, Sz * Bz, Gz, Ez, bih_e, bhh_e);
    }
    {
        dim3 grid(Gz / 128, (TDz * Bz + 127) / 128);
        sgemm_nt_kernel<<<grid, 256>>>(p_Xd, Wih_d, p_Pd, TDz * Bz, Gz, Ez, bih_d, bhh_d);
    }

    // 3b) W_out bf16 split (independent of everything else)
    convert_w_kernel<<<4096, 256>>>(W_out, p_Whi, p_Wlo, Vz * Hz / 4);

    // 4+5+6) recurrences + latent head, one persistent kernel
    lstm_persistent<<<NBLK, 256>>>(Whh_e, Whh_d, p_Pe, p_Pd, p_hse, p_hsd,
                                   tokens, W_mu, b_mu, W_lv, b_lv, epsv,
                                   W_l2h, b_l2h, out_mean, out_lv);

    // 6b) hd bf16 split
    convert_a_kernel<<<1024, 256>>>(p_hsd, p_Ahi, p_Alo);

    // 7) logits via mma.sync bf16 3-split
    cudaFuncSetAttribute(mma_logits_kernel, cudaFuncAttributeMaxDynamicSharedMemorySize, SMEM_MMA);
    {
        dim3 grid(32, 250);
        mma_logits_kernel<<<grid, 256, SMEM_MMA>>>(p_Ahi, p_Alo, p_Whi, p_Wlo, b_out, out_logits);
    }
}